// round 2
// baseline (speedup 1.0000x reference)
#include <cuda_runtime.h>
#include <cstdint>

#define NN 50000
#define RR 16
#define HH 64
#define CC 16
#define EE 800000

// ---------------- device scratch (static; no allocation) ----------------
__device__ float g_Y[(size_t)NN * RR * HH];   // per-(node,relation) feature sums, 204.8 MB
__device__ int   g_cnt[NN * RR];              // edge counts per (dst, relation)
__device__ float g_inv[NN * RR];              // 1/cnt (0 if cnt==0)
__device__ float g_X1[(size_t)NN * HH];       // hidden layer activations

// ---------------- utility kernels ----------------
__global__ void zero_Y_k() {
    size_t i = (size_t)blockIdx.x * blockDim.x + threadIdx.x;
    if (i < (size_t)NN * RR * HH / 4)
        ((float4*)g_Y)[i] = make_float4(0.f, 0.f, 0.f, 0.f);
}

__global__ void zero_cnt_k() {
    int i = blockIdx.x * blockDim.x + threadIdx.x;
    if (i < NN * RR) g_cnt[i] = 0;
}

__global__ void count_k(const int* __restrict__ ei, const int* __restrict__ et) {
    int e = blockIdx.x * blockDim.x + threadIdx.x;
    if (e < EE) atomicAdd(&g_cnt[ei[EE + e] * RR + et[e]], 1);
}

__global__ void inv_k() {
    int i = blockIdx.x * blockDim.x + threadIdx.x;
    if (i < NN * RR) {
        int c = g_cnt[i];
        g_inv[i] = (c > 0) ? 1.0f / (float)c : 0.0f;
    }
}

// ---------------- edge scatter: Y[dst, type, :] += x[src, :] ----------------
// One thread per (edge, float4-chunk). 16 threads cover an edge's 64 floats.
template <bool USE_X1>
__global__ void scatter_t(const int* __restrict__ ei, const int* __restrict__ et,
                          const float4* __restrict__ xin) {
    unsigned t = blockIdx.x * blockDim.x + threadIdx.x;
    unsigned e = t >> 4;
    unsigned j = t & 15;
    if (e < EE) {
        const float4* x = USE_X1 ? (const float4*)g_X1 : xin;
        int src = ei[e];
        int dst = ei[EE + e];
        int r   = et[e];
        float4 v = x[(size_t)src * 16 + j];
        float* p = &g_Y[((size_t)dst * RR + r) * HH + j * 4];
        asm volatile("red.global.add.v4.f32 [%0], {%1,%2,%3,%4};"
                     :: "l"(__cvta_generic_to_global(p)),
                        "f"(v.x), "f"(v.y), "f"(v.z), "f"(v.w)
                     : "memory");
    }
}

// ---------------- layer 1 GEMM: X1 = relu( [Y_norm | x] @ [W1 ; root1] + b1 ) ----------------
// M=NN, K=1088 (17 chunks of 64), N=64. BM=64, BN=64, BK=64, 256 threads, 4x4 micro-tile.
__global__ __launch_bounds__(256) void gemm1_k(const float* __restrict__ x,
                                               const float* __restrict__ W1,
                                               const float* __restrict__ root1,
                                               const float* __restrict__ b1) {
    __shared__ float As[64][65];
    __shared__ float Bs[64][64];
    int tid = threadIdx.x;
    int tx = tid & 15;        // output column group (cols tx*4..tx*4+3)
    int ty = tid >> 4;        // output row group (rows ty*4..ty*4+3)
    int v0 = blockIdx.x * 64;

    float acc[4][4] = {};

    for (int t = 0; t < 17; ++t) {
        // --- load B tile (64x64 chunk of stacked weights), fully coalesced ---
        const float* Bsrc = (t < 16) ? (W1 + (size_t)t * 4096) : root1;
        #pragma unroll
        for (int i = 0; i < 4; ++i) {
            int idx = tid + i * 256;            // float4 index, 0..1023
            float4 bv = ((const float4*)Bsrc)[idx];
            *(float4*)&Bs[idx >> 4][(idx & 15) * 4] = bv;
        }
        // --- load A tile with per-(node,relation) mean normalization ---
        #pragma unroll
        for (int i = 0; i < 4; ++i) {
            int idx = tid + i * 256;            // 0..1023 float4 units of 64x64 tile
            int node = idx >> 4;
            int kq   = idx & 15;
            int v = v0 + node;
            float4 av = make_float4(0.f, 0.f, 0.f, 0.f);
            float sc = 0.f;
            if (v < NN) {
                if (t < 16) {
                    av = *(const float4*)&g_Y[(size_t)v * 1024 + t * 64 + kq * 4];
                    sc = g_inv[v * RR + t];
                } else {
                    av = ((const float4*)(x + (size_t)v * 64))[kq];
                    sc = 1.0f;
                }
            }
            As[node][kq * 4 + 0] = av.x * sc;
            As[node][kq * 4 + 1] = av.y * sc;
            As[node][kq * 4 + 2] = av.z * sc;
            As[node][kq * 4 + 3] = av.w * sc;
        }
        __syncthreads();
        // --- inner product ---
        #pragma unroll 16
        for (int kk = 0; kk < 64; ++kk) {
            float a[4];
            #pragma unroll
            for (int i = 0; i < 4; ++i) a[i] = As[ty * 4 + i][kk];
            float4 bv = *(const float4*)&Bs[kk][tx * 4];
            #pragma unroll
            for (int i = 0; i < 4; ++i) {
                acc[i][0] += a[i] * bv.x;
                acc[i][1] += a[i] * bv.y;
                acc[i][2] += a[i] * bv.z;
                acc[i][3] += a[i] * bv.w;
            }
        }
        __syncthreads();
    }

    // --- epilogue: + bias, relu, store hidden ---
    int c0 = tx * 4;
    float4 bias = make_float4(b1[c0], b1[c0 + 1], b1[c0 + 2], b1[c0 + 3]);
    #pragma unroll
    for (int i = 0; i < 4; ++i) {
        int v = v0 + ty * 4 + i;
        if (v < NN) {
            float4 o;
            o.x = fmaxf(acc[i][0] + bias.x, 0.f);
            o.y = fmaxf(acc[i][1] + bias.y, 0.f);
            o.z = fmaxf(acc[i][2] + bias.z, 0.f);
            o.w = fmaxf(acc[i][3] + bias.w, 0.f);
            *(float4*)&g_X1[(size_t)v * 64 + c0] = o;
        }
    }
}

// ---------------- layer 2 GEMM: out = [Y_norm | X1] @ [W2 ; root2] + b2 ----------------
// M=NN, K=1088 (34 chunks of 32), N=16. BM=256, BN=16, BK=32, 256 threads, 4x4 micro-tile.
__global__ __launch_bounds__(256) void gemm2_k(const float* __restrict__ W2,
                                               const float* __restrict__ root2,
                                               const float* __restrict__ b2,
                                               float* __restrict__ out) {
    __shared__ float As[256][33];
    __shared__ float Bs[32][16];
    int tid = threadIdx.x;
    int tx = tid & 3;         // cols tx*4..tx*4+3
    int ty = tid >> 2;        // rows ty*4..ty*4+3 (0..63)
    int v0 = blockIdx.x * 256;

    float acc[4][4] = {};

    for (int t = 0; t < 34; ++t) {
        // --- load B tile (32x16) ---
        if (tid < 128) {
            const float* Bsrc = (t < 32) ? (W2 + (size_t)(t >> 1) * 1024 + (t & 1) * 32 * 16)
                                         : (root2 + (size_t)(t - 32) * 32 * 16);
            float4 bv = ((const float4*)Bsrc)[tid];
            *(float4*)&Bs[tid >> 2][(tid & 3) * 4] = bv;
        }
        // --- load A tile (256 nodes x 32 k) ---
        #pragma unroll
        for (int i = 0; i < 8; ++i) {
            int idx = tid + i * 256;            // float4 index, 0..2047
            int node = idx >> 3;
            int kq   = idx & 7;
            int v = v0 + node;
            float4 av = make_float4(0.f, 0.f, 0.f, 0.f);
            float sc = 0.f;
            if (v < NN) {
                if (t < 32) {
                    av = *(const float4*)&g_Y[(size_t)v * 1024 + t * 32 + kq * 4];
                    sc = g_inv[v * RR + (t >> 1)];
                } else {
                    av = *(const float4*)&g_X1[(size_t)v * 64 + (t - 32) * 32 + kq * 4];
                    sc = 1.0f;
                }
            }
            As[node][kq * 4 + 0] = av.x * sc;
            As[node][kq * 4 + 1] = av.y * sc;
            As[node][kq * 4 + 2] = av.z * sc;
            As[node][kq * 4 + 3] = av.w * sc;
        }
        __syncthreads();
        #pragma unroll
        for (int kk = 0; kk < 32; ++kk) {
            float a[4];
            #pragma unroll
            for (int i = 0; i < 4; ++i) a[i] = As[ty * 4 + i][kk];
            float4 bv = *(const float4*)&Bs[kk][tx * 4];
            #pragma unroll
            for (int i = 0; i < 4; ++i) {
                acc[i][0] += a[i] * bv.x;
                acc[i][1] += a[i] * bv.y;
                acc[i][2] += a[i] * bv.z;
                acc[i][3] += a[i] * bv.w;
            }
        }
        __syncthreads();
    }

    int c0 = tx * 4;
    float4 bias = make_float4(b2[c0], b2[c0 + 1], b2[c0 + 2], b2[c0 + 3]);
    #pragma unroll
    for (int i = 0; i < 4; ++i) {
        int v = v0 + ty * 4 + i;
        if (v < NN) {
            float4 o;
            o.x = acc[i][0] + bias.x;
            o.y = acc[i][1] + bias.y;
            o.z = acc[i][2] + bias.z;
            o.w = acc[i][3] + bias.w;
            *(float4*)&out[(size_t)v * 16 + c0] = o;
        }
    }
}

// ---------------- launch ----------------
extern "C" void kernel_launch(void* const* d_in, const int* in_sizes, int n_in,
                              void* d_out, int out_size) {
    const int*   ei    = (const int*)d_in[0];
    const int*   et    = (const int*)d_in[1];
    const float* x     = (const float*)d_in[2];
    const float* W1    = (const float*)d_in[3];
    const float* root1 = (const float*)d_in[4];
    const float* b1    = (const float*)d_in[5];
    const float* W2    = (const float*)d_in[6];
    const float* root2 = (const float*)d_in[7];
    const float* b2    = (const float*)d_in[8];
    float* out = (float*)d_out;

    (void)in_sizes; (void)n_in; (void)out_size;

    const int Z_Y_BLOCKS  = (int)(((size_t)NN * RR * HH / 4 + 255) / 256); // 50000
    const int SC_BLOCKS   = (int)(((size_t)EE * 16 + 255) / 256);          // 50000

    // counts / inverse means (shared by both layers)
    zero_cnt_k<<<(NN * RR + 255) / 256, 256>>>();
    count_k<<<(EE + 255) / 256, 256>>>(ei, et);
    inv_k<<<(NN * RR + 255) / 256, 256>>>();

    // ---- layer 1 ----
    zero_Y_k<<<Z_Y_BLOCKS, 256>>>();
    scatter_t<false><<<SC_BLOCKS, 256>>>(ei, et, (const float4*)x);
    gemm1_k<<<(NN + 63) / 64, 256>>>(x, W1, root1, b1);

    // ---- layer 2 ----
    zero_Y_k<<<Z_Y_BLOCKS, 256>>>();
    scatter_t<true><<<SC_BLOCKS, 256>>>(ei, et, nullptr);
    gemm2_k<<<(NN + 255) / 256, 256>>>(W2, root2, b2, out);
}